// round 14
// baseline (speedup 1.0000x reference)
#include <cuda_runtime.h>

// StackMemory degenerate form:
//   out[0, t, 0, h] = softmax(x_t @ W^T + b)[0] * sigmoid(x_t @ D)   (all h)
//   out[0, t, d, h] = 0   for d >= 1
// Store-bandwidth bound. Block-level role split (champion, 61.9 us):
//   blocks [0, NVBLK)          : value blocks, 1 warp per timestep (8 t / block)
//   blocks [NVBLK, NVBLK+T_LEN): zero blocks, one t each, streaming __stcs
// FINAL. Measured write-path matrix: STG (hints/width/occupancy) 6.0-6.2 TB/s
// ceiling; CE memset 7.2 TB/s but serializes (no graph overlap); TMA bulk
// slower (path-independent cap); st.bulk traps. This kernel sits on the SM
// write ceiling with DRAM 78%, nothing else saturated.

#define T_LEN 8192
#define HID   400
#define DEPTH 32
#define NTHREADS 256
#define NVBLK (T_LEN / 8)          // 1024 value blocks, 8 warps each
#define ROWVEC (HID / 4)           // 100 float4 per (t, d) row
#define TVEC  (DEPTH * HID / 4)    // 3200 float4 per t

__global__ __launch_bounds__(NTHREADS)
void stackmem_kernel(const float4* __restrict__ x4,  // (T, 100)
                     const float4* __restrict__ W4,  // (3, 100)
                     const float*  __restrict__ b,   // (3,)
                     const float4* __restrict__ D4,  // (100,)
                     float4* __restrict__ out4)      // (T, 32, 100)
{
    const int bid = blockIdx.x;
    const int tid = threadIdx.x;

    if (bid >= NVBLK) {
        // ================= zero block: one timestep's d>=1 region ========
        const int t = bid - NVBLK;
        float4* o = out4 + (size_t)t * TVEC + ROWVEC;   // skip d=0 row
        const float4 z = make_float4(0.f, 0.f, 0.f, 0.f);
        const int N = TVEC - ROWVEC;                    // 3100
        #pragma unroll 4
        for (int i = tid; i < N; i += NTHREADS) {
            __stcs(o + i, z);
        }
        return;
    }

    // ==================== value block: 1 warp per t ======================
    const int warp = tid >> 5;
    const int lane = tid & 31;
    const int t = bid * 8 + warp;

    const float4* xt = x4 + (size_t)t * ROWVEC;

    float s0 = 0.f, s1 = 0.f, s2 = 0.f, sd = 0.f;
    #pragma unroll
    for (int base = 0; base < ROWVEC; base += 32) {
        int i = base + lane;
        if (i < ROWVEC) {
            float4 xv = xt[i];
            float4 w0 = W4[i];
            float4 w1 = W4[ROWVEC + i];
            float4 w2 = W4[2 * ROWVEC + i];
            float4 dv = D4[i];
            s0 = fmaf(xv.x, w0.x, fmaf(xv.y, w0.y, fmaf(xv.z, w0.z, fmaf(xv.w, w0.w, s0))));
            s1 = fmaf(xv.x, w1.x, fmaf(xv.y, w1.y, fmaf(xv.z, w1.z, fmaf(xv.w, w1.w, s1))));
            s2 = fmaf(xv.x, w2.x, fmaf(xv.y, w2.y, fmaf(xv.z, w2.z, fmaf(xv.w, w2.w, s2))));
            sd = fmaf(xv.x, dv.x, fmaf(xv.y, dv.y, fmaf(xv.z, dv.z, fmaf(xv.w, dv.w, sd))));
        }
    }

    #pragma unroll
    for (int off = 16; off > 0; off >>= 1) {
        s0 += __shfl_down_sync(0xffffffffu, s0, off);
        s1 += __shfl_down_sync(0xffffffffu, s1, off);
        s2 += __shfl_down_sync(0xffffffffu, s2, off);
        sd += __shfl_down_sync(0xffffffffu, sd, off);
    }

    float val;
    if (lane == 0) {
        float l0 = s0 + b[0];
        float l1 = s1 + b[1];
        float l2 = s2 + b[2];
        float m  = fmaxf(l0, fmaxf(l1, l2));
        float e0 = __expf(l0 - m);
        float e1 = __expf(l1 - m);
        float e2 = __expf(l2 - m);
        float push = e0 / (e0 + e1 + e2);
        float pv   = 1.0f / (1.0f + __expf(-sd));
        val = push * pv;
    }
    val = __shfl_sync(0xffffffffu, val, 0);

    const float4 v4 = make_float4(val, val, val, val);
    float4* o = out4 + (size_t)t * TVEC;    // d=0 row
    #pragma unroll
    for (int base = 0; base < ROWVEC; base += 32) {
        int i = base + lane;
        if (i < ROWVEC) o[i] = v4;
    }
}

extern "C" void kernel_launch(void* const* d_in, const int* in_sizes, int n_in,
                              void* d_out, int out_size) {
    const float4* x = (const float4*)d_in[0];  // hidden_state (1, 8192, 400)
    const float4* W = (const float4*)d_in[1];  // W_ap (3, 400)
    const float*  b = (const float*) d_in[2];  // b_ap (3,)
    const float4* D = (const float4*)d_in[3];  // D (1, 400)
    float4* out = (float4*)d_out;              // (1, 8192, 32, 400)

    stackmem_kernel<<<NVBLK + T_LEN, NTHREADS>>>(x, W, b, D, out);
}

// round 15
// speedup vs baseline: 1.0233x; 1.0233x over previous
#include <cuda_runtime.h>

// StackMemory degenerate form:
//   out[0, t, 0, h] = softmax(x_t @ W^T + b)[0] * sigmoid(x_t @ D)   (all h)
//   out[0, t, d, h] = 0   for d >= 1
// Store-bandwidth bound. R14: same champion role-split store pattern, block
// size halved to 128 threads for finer wave-tail drain + 12 blocks/SM:
//   blocks [0, NVBLK)   : value blocks, 1 warp per timestep (4 t / block)
//   blocks [NVBLK, ...) : zero blocks, HALF a timestep's d>=1 region each
//                         (1550 float4, ~12 iterations -- same per-thread
//                          work as the 256-thread champion)

#define T_LEN 8192
#define HID   400
#define DEPTH 32
#define NTHREADS 128
#define NVBLK (T_LEN / 4)          // 2048 value blocks, 4 warps each
#define NZBLK (T_LEN * 2)          // 16384 zero blocks, half a t each
#define ROWVEC (HID / 4)           // 100 float4 per (t, d) row
#define TVEC  (DEPTH * HID / 4)    // 3200 float4 per t
#define ZHALF ((TVEC - ROWVEC) / 2) // 1550 float4 per zero block

__global__ __launch_bounds__(NTHREADS)
void stackmem_kernel(const float4* __restrict__ x4,  // (T, 100)
                     const float4* __restrict__ W4,  // (3, 100)
                     const float*  __restrict__ b,   // (3,)
                     const float4* __restrict__ D4,  // (100,)
                     float4* __restrict__ out4)      // (T, 32, 100)
{
    const int bid = blockIdx.x;
    const int tid = threadIdx.x;

    if (bid >= NVBLK) {
        // ========= zero block: half of one timestep's d>=1 region ========
        const int z = bid - NVBLK;          // 0 .. NZBLK-1
        const int t = z >> 1;
        const int half = z & 1;
        float4* o = out4 + (size_t)t * TVEC + ROWVEC + half * ZHALF;
        const float4 zz = make_float4(0.f, 0.f, 0.f, 0.f);
        #pragma unroll 4
        for (int i = tid; i < ZHALF; i += NTHREADS) {
            __stcs(o + i, zz);
        }
        return;
    }

    // ==================== value block: 1 warp per t ======================
    const int warp = tid >> 5;
    const int lane = tid & 31;
    const int t = bid * 4 + warp;

    const float4* xt = x4 + (size_t)t * ROWVEC;

    float s0 = 0.f, s1 = 0.f, s2 = 0.f, sd = 0.f;
    #pragma unroll
    for (int base = 0; base < ROWVEC; base += 32) {
        int i = base + lane;
        if (i < ROWVEC) {
            float4 xv = xt[i];
            float4 w0 = W4[i];
            float4 w1 = W4[ROWVEC + i];
            float4 w2 = W4[2 * ROWVEC + i];
            float4 dv = D4[i];
            s0 = fmaf(xv.x, w0.x, fmaf(xv.y, w0.y, fmaf(xv.z, w0.z, fmaf(xv.w, w0.w, s0))));
            s1 = fmaf(xv.x, w1.x, fmaf(xv.y, w1.y, fmaf(xv.z, w1.z, fmaf(xv.w, w1.w, s1))));
            s2 = fmaf(xv.x, w2.x, fmaf(xv.y, w2.y, fmaf(xv.z, w2.z, fmaf(xv.w, w2.w, s2))));
            sd = fmaf(xv.x, dv.x, fmaf(xv.y, dv.y, fmaf(xv.z, dv.z, fmaf(xv.w, dv.w, sd))));
        }
    }

    #pragma unroll
    for (int off = 16; off > 0; off >>= 1) {
        s0 += __shfl_down_sync(0xffffffffu, s0, off);
        s1 += __shfl_down_sync(0xffffffffu, s1, off);
        s2 += __shfl_down_sync(0xffffffffu, s2, off);
        sd += __shfl_down_sync(0xffffffffu, sd, off);
    }

    float val;
    if (lane == 0) {
        float l0 = s0 + b[0];
        float l1 = s1 + b[1];
        float l2 = s2 + b[2];
        float m  = fmaxf(l0, fmaxf(l1, l2));
        float e0 = __expf(l0 - m);
        float e1 = __expf(l1 - m);
        float e2 = __expf(l2 - m);
        float push = e0 / (e0 + e1 + e2);
        float pv   = 1.0f / (1.0f + __expf(-sd));
        val = push * pv;
    }
    val = __shfl_sync(0xffffffffu, val, 0);

    const float4 v4 = make_float4(val, val, val, val);
    float4* o = out4 + (size_t)t * TVEC;    // d=0 row
    #pragma unroll
    for (int base = 0; base < ROWVEC; base += 32) {
        int i = base + lane;
        if (i < ROWVEC) o[i] = v4;
    }
}

extern "C" void kernel_launch(void* const* d_in, const int* in_sizes, int n_in,
                              void* d_out, int out_size) {
    const float4* x = (const float4*)d_in[0];  // hidden_state (1, 8192, 400)
    const float4* W = (const float4*)d_in[1];  // W_ap (3, 400)
    const float*  b = (const float*) d_in[2];  // b_ap (3,)
    const float4* D = (const float4*)d_in[3];  // D (1, 400)
    float4* out = (float4*)d_out;              // (1, 8192, 32, 400)

    stackmem_kernel<<<NVBLK + NZBLK, NTHREADS>>>(x, W, b, D, out);
}